// round 12
// baseline (speedup 1.0000x reference)
#include <cuda_runtime.h>
#include <cuda_bf16.h>
#include <cuda_fp16.h>
#include <cstdint>

// Fixed shapes: B=2, H=8, N=256, D=64.
// Grid: 8192 CTAs of 128 thr (4 warps): CTA = (query bhq, k-half).
// Warp w owns k-rows [128*half + 32w, +32).  GEMM1 bf16 hi/lo 3-product,
// GEMM2 fp16 1-product, per-warp online max; cross-CTA combine kernel.
#define NQ 256
#define DD 64
#define NPANEL 4

#define SWZ(x) ((x) ^ (((x) >> 3) & 0x70))

static constexpr uint32_t OFF_K2H  = 0;        // [128 k][64 d] bf16 hi (16 KB)
static constexpr uint32_t OFF_K2L  = 16384;
static constexpr uint32_t OFF_QHH  = 32768;    // [64 j][64 d] bf16 hi (8 KB)
static constexpr uint32_t OFF_QHL  = 40960;
static constexpr uint32_t OFF_V1H  = 49152;    // [64 j][64 d] fp16 (8 KB)
static constexpr uint32_t OFF_RAWK = 57344;    // 16 KB raw fp32 K1 panel (single buf)
static constexpr uint32_t OFF_RAWV = 73728;    // 16 KB raw fp32 V1 panel
static constexpr uint32_t OFF_SRED = 90112;    // [4 warps][64 d] fp32 (1 KB)
static constexpr uint32_t OFF_SLP  = 91136;    // [4] fp32 lsum
static constexpr uint32_t OFF_SM   = 91152;    // [4] fp32 per-warp max
static constexpr uint32_t SMEM_BYTES = 91168;  // ~89 KB -> 2 CTAs/SM

// per-(query, half): [0..63]=num, [64]=lsum, [65]=max  (2.2 MB scratch)
__device__ float g_part[2 * 8 * NQ][2][66];

// ---------------- PTX helpers ----------------------------------------------
__device__ __forceinline__ uint32_t smem_u32(const void* p) {
    uint32_t a;
    asm("{ .reg .u64 t; cvta.to.shared.u64 t, %1; cvt.u32.u64 %0, t; }" : "=r"(a) : "l"(p));
    return a;
}
__device__ __forceinline__ float ex2f(float x) {
    float y; asm("ex2.approx.ftz.f32 %0, %1;" : "=f"(y) : "f"(x)); return y;
}
__device__ __forceinline__ void cp16(uint32_t dst, const void* src) {
    asm volatile("cp.async.cg.shared.global [%0], [%1], 16;" :: "r"(dst), "l"(src));
}
__device__ __forceinline__ void cp_commit() { asm volatile("cp.async.commit_group;"); }
__device__ __forceinline__ void cp_wait0()  { asm volatile("cp.async.wait_group 0;" ::: "memory"); }
__device__ __forceinline__ void ldsm_x4(uint32_t* r, uint32_t addr) {
    asm volatile("ldmatrix.sync.aligned.m8n8.x4.shared.b16 {%0,%1,%2,%3}, [%4];"
                 : "=r"(r[0]), "=r"(r[1]), "=r"(r[2]), "=r"(r[3]) : "r"(addr));
}
__device__ __forceinline__ void ldsm_x4_t(uint32_t* r, uint32_t addr) {
    asm volatile("ldmatrix.sync.aligned.m8n8.x4.trans.shared.b16 {%0,%1,%2,%3}, [%4];"
                 : "=r"(r[0]), "=r"(r[1]), "=r"(r[2]), "=r"(r[3]) : "r"(addr));
}
__device__ __forceinline__ void mma_bf(float* c, const uint32_t* a, uint32_t b0, uint32_t b1) {
    asm("mma.sync.aligned.m16n8k16.row.col.f32.bf16.bf16.f32 "
        "{%0,%1,%2,%3}, {%4,%5,%6,%7}, {%8,%9}, {%0,%1,%2,%3};"
        : "+f"(c[0]), "+f"(c[1]), "+f"(c[2]), "+f"(c[3])
        : "r"(a[0]), "r"(a[1]), "r"(a[2]), "r"(a[3]), "r"(b0), "r"(b1));
}
__device__ __forceinline__ void mma_hf(float* c, const uint32_t* a, uint32_t b0, uint32_t b1) {
    asm("mma.sync.aligned.m16n8k16.row.col.f32.f16.f16.f32 "
        "{%0,%1,%2,%3}, {%4,%5,%6,%7}, {%8,%9}, {%0,%1,%2,%3};"
        : "+f"(c[0]), "+f"(c[1]), "+f"(c[2]), "+f"(c[3])
        : "r"(a[0]), "r"(a[1]), "r"(a[2]), "r"(a[3]), "r"(b0), "r"(b1));
}
__device__ __forceinline__ void split2(float x, float y, uint32_t& h, uint32_t& l) {
    __nv_bfloat162 h2 = __floats2bfloat162_rn(x, y);
    __nv_bfloat162 l2 = __floats2bfloat162_rn(x - __low2float(h2), y - __high2float(h2));
    h = *(uint32_t*)&h2; l = *(uint32_t*)&l2;
}
__device__ __forceinline__ uint32_t packh2_sat(float x, float y) {   // x -> low half
    uint32_t r;
    asm("cvt.rn.satfinite.f16x2.f32 %0, %1, %2;" : "=r"(r) : "f"(y), "f"(x));
    return r;
}

// ---------------- Main kernel ----------------------------------------------
__global__ __launch_bounds__(128, 2)
void trisimp_half_kernel(const float* __restrict__ q,  const float* __restrict__ k1,
                         const float* __restrict__ v1, const float* __restrict__ k2,
                         const float* __restrict__ v2)
{
    extern __shared__ char smem[];
    const uint32_t sb = smem_u32(smem);
    const int tid = threadIdx.x, w = tid >> 5, lid = tid & 31;
    const int g = lid >> 2, t = lid & 3;

    const int bid = blockIdx.x;
    const int bhq = bid >> 1, half = bid & 1;
    const int qi = bhq & 255, bh = bhq >> 8;
    const int kbase = half * 128;
    const size_t base = (size_t)bh * NQ * DD;
    const float* Qrow = q  + base + (size_t)qi * DD;
    const float* K1g  = k1 + base;
    const float* V1g  = v1 + base;
    const float* K2h  = k2 + base + (size_t)kbase * DD;   // this CTA's k-half
    const float* V2g  = v2 + base;

    // ---- prefetch panel 0 raw K1/V1 (16 KB each) ----
    {
        const char* gK = (const char*)K1g;
        const char* gV = (const char*)V1g;
        for (int i = tid; i < 1024; i += 128) {
            cp16(sb + OFF_RAWK + (uint32_t)i * 16, gK + (size_t)i * 16);
            cp16(sb + OFF_RAWV + (uint32_t)i * 16, gV + (size_t)i * 16);
        }
        cp_commit();
    }

    const int dp = tid & 31;
    // ---- stage this half's K2 hi/lo: [128 k][64 d] ----
    {
        const float2* K2g2 = (const float2*)K2h;
        for (int e2 = tid; e2 < 128 * 32; e2 += 128) {
            const int r = e2 >> 5;
            const float2 x = K2g2[e2];
            uint32_t h, l; split2(x.x, x.y, h, l);
            const uint32_t off = SWZ((uint32_t)r * 128 + (uint32_t)dp * 4);
            *(uint32_t*)(smem + OFF_K2H + off) = h;
            *(uint32_t*)(smem + OFF_K2L + off) = l;
        }
    }

    const float2 qme = ((const float2*)Qrow)[dp];
    const float qx = qme.x * 1.4426950408889634f;
    const float qy = qme.y * 1.4426950408889634f;

    const uint32_t lmA_r = (uint32_t)(lid & 15), lmA_c = (uint32_t)(lid >> 4) * 16;
    const uint32_t lmB_r = (uint32_t)((lid >> 4) * 8 + (lid & 7)), lmB_c = (uint32_t)((lid >> 3) & 1) * 16;

    float o[2][8][4];
    #pragma unroll
    for (int mt = 0; mt < 2; ++mt)
        #pragma unroll
        for (int nt = 0; nt < 8; ++nt)
            #pragma unroll
            for (int r = 0; r < 4; ++r) o[mt][nt][r] = 0.f;
    float lsum = 0.f;
    float mrun = -1e30f;

    #pragma unroll 1
    for (int p = 0; p < NPANEL; ++p) {
        cp_wait0();
        __syncthreads();                 // raw p landed; QH/V1 free (all GEMM2 readers done)

        // ---- convert raw panel p: Qh (bf16 hi/lo) + V1 (fp16) ----
        {
            const float2* rk = (const float2*)(smem + OFF_RAWK);
            const float2* rv = (const float2*)(smem + OFF_RAWV);
            for (int e2 = tid; e2 < 64 * 32; e2 += 128) {
                const int r = e2 >> 5;
                const uint32_t off = SWZ((uint32_t)r * 128 + (uint32_t)dp * 4);
                {
                    const float2 x = rk[e2];
                    uint32_t h, l; split2(qx * x.x, qy * x.y, h, l);
                    *(uint32_t*)(smem + OFF_QHH + off) = h;
                    *(uint32_t*)(smem + OFF_QHL + off) = l;
                }
                {
                    const float2 x = rv[e2];
                    const __half2 hh = __floats2half2_rn(x.x, x.y);
                    *(uint32_t*)(smem + OFF_V1H + off) = *(const uint32_t*)&hh;
                }
            }
        }
        __syncthreads();                 // converted panel ready; raw buf fully read
        if (p < NPANEL - 1) {            // prefetch p+1 (overlaps GEMM phases)
            const char* gK = (const char*)(K1g + (size_t)(p + 1) * 64 * DD);
            const char* gV = (const char*)(V1g + (size_t)(p + 1) * 64 * DD);
            for (int i = tid; i < 1024; i += 128) {
                cp16(sb + OFF_RAWK + (uint32_t)i * 16, gK + (size_t)i * 16);
                cp16(sb + OFF_RAWV + (uint32_t)i * 16, gV + (size_t)i * 16);
            }
            cp_commit();
        }

        // ---- GEMM1: S[k32(w), j64] in log2 units (bf16 hi/lo, 3 products) ----
        float s[2][8][4];
        #pragma unroll
        for (int mt = 0; mt < 2; ++mt)
            #pragma unroll
            for (int nt = 0; nt < 8; ++nt)
                #pragma unroll
                for (int r = 0; r < 4; ++r) s[mt][nt][r] = 0.f;

        #pragma unroll
        for (int kc = 0; kc < 4; ++kc) {
            uint32_t aH[2][4], aL[2][4];
            #pragma unroll
            for (int mt = 0; mt < 2; ++mt) {
                const uint32_t rb = (uint32_t)(32 * w + 16 * mt + lmA_r) * 128
                                  + (uint32_t)kc * 32 + lmA_c;
                ldsm_x4(aH[mt], sb + OFF_K2H + SWZ(rb));
                ldsm_x4(aL[mt], sb + OFF_K2L + SWZ(rb));
            }
            #pragma unroll
            for (int cp = 0; cp < 4; ++cp) {
                uint32_t bH[4], bL[4];
                const uint32_t rb = (uint32_t)(16 * cp + lmB_r) * 128
                                  + (uint32_t)kc * 32 + lmB_c;
                ldsm_x4(bH, sb + OFF_QHH + SWZ(rb));
                ldsm_x4(bL, sb + OFF_QHL + SWZ(rb));
                #pragma unroll
                for (int h = 0; h < 2; ++h)
                    #pragma unroll
                    for (int mt = 0; mt < 2; ++mt)
                        mma_bf(s[mt][2*cp+h], aH[mt], bH[2*h], bH[2*h+1]);
                #pragma unroll
                for (int h = 0; h < 2; ++h)
                    #pragma unroll
                    for (int mt = 0; mt < 2; ++mt)
                        mma_bf(s[mt][2*cp+h], aH[mt], bL[2*h], bL[2*h+1]);
                #pragma unroll
                for (int h = 0; h < 2; ++h)
                    #pragma unroll
                    for (int mt = 0; mt < 2; ++mt)
                        mma_bf(s[mt][2*cp+h], aL[mt], bH[2*h], bH[2*h+1]);
            }
        }

        // ---- online max update ----
        {
            float pm = s[0][0][0];
            #pragma unroll
            for (int mt = 0; mt < 2; ++mt)
                #pragma unroll
                for (int nt = 0; nt < 8; ++nt)
                    #pragma unroll
                    for (int r = 0; r < 4; ++r) pm = fmaxf(pm, s[mt][nt][r]);
            #pragma unroll
            for (int m = 16; m; m >>= 1)
                pm = fmaxf(pm, __shfl_xor_sync(0xffffffffu, pm, m));
            const float mnew = fmaxf(mrun, pm);
            const float rsc = ex2f(mrun - mnew);
            lsum *= rsc;
            #pragma unroll
            for (int mt = 0; mt < 2; ++mt)
                #pragma unroll
                for (int nt = 0; nt < 8; ++nt)
                    #pragma unroll
                    for (int r = 0; r < 4; ++r) o[mt][nt][r] *= rsc;
            mrun = mnew;
        }

        // ---- exp2 -> fp16 P, GEMM2 fp16 1-product ----
        #pragma unroll
        for (int c = 0; c < 4; ++c) {
            uint32_t paH[2][4];
            #pragma unroll
            for (int mt = 0; mt < 2; ++mt) {
                #pragma unroll
                for (int h = 0; h < 2; ++h) {
                    float* cc = s[mt][2 * c + h];
                    const float p0 = ex2f(cc[0] - mrun);
                    const float p1 = ex2f(cc[1] - mrun);
                    const float p2 = ex2f(cc[2] - mrun);
                    const float p3 = ex2f(cc[3] - mrun);
                    lsum += (p0 + p1) + (p2 + p3);
                    paH[mt][2*h]   = packh2_sat(p0, p1);
                    paH[mt][2*h+1] = packh2_sat(p2, p3);
                }
            }
            #pragma unroll
            for (int ntp = 0; ntp < 4; ++ntp) {
                uint32_t vH[4];
                const uint32_t rb = (uint32_t)(16 * c + lmA_r) * 128
                                  + (uint32_t)ntp * 32 + lmA_c;
                ldsm_x4_t(vH, sb + OFF_V1H + SWZ(rb));
                #pragma unroll
                for (int h = 0; h < 2; ++h)
                    #pragma unroll
                    for (int mt = 0; mt < 2; ++mt)
                        mma_hf(o[mt][2*ntp+h], paH[mt], vH[2*h], vH[2*h+1]);
            }
        }
    }

    // ---- epilogue: per-warp num/lsum/max -> CTA partial -> global scratch ----
    float* sRed = (float*)(smem + OFF_SRED);
    float* sLp  = (float*)(smem + OFF_SLP);
    float* sM   = (float*)(smem + OFF_SM);
    {
        const int k0 = kbase + 32 * w + g;
        #pragma unroll
        for (int nt = 0; nt < 8; ++nt) {
            const int d0 = 8 * nt + 2 * t;
            const float2 vA = *(const float2*)(V2g + (size_t)(k0)      * DD + d0);
            const float2 vB = *(const float2*)(V2g + (size_t)(k0 + 8)  * DD + d0);
            const float2 vC = *(const float2*)(V2g + (size_t)(k0 + 16) * DD + d0);
            const float2 vD = *(const float2*)(V2g + (size_t)(k0 + 24) * DD + d0);
            float r0 = o[0][nt][0]*vA.x + o[0][nt][2]*vB.x + o[1][nt][0]*vC.x + o[1][nt][2]*vD.x;
            float r1 = o[0][nt][1]*vA.y + o[0][nt][3]*vB.y + o[1][nt][1]*vC.y + o[1][nt][3]*vD.y;
            #pragma unroll
            for (int m = 4; m <= 16; m <<= 1) {
                r0 += __shfl_xor_sync(0xffffffffu, r0, m);
                r1 += __shfl_xor_sync(0xffffffffu, r1, m);
            }
            if (g == 0) *(float2*)(sRed + w * 64 + d0) = make_float2(r0, r1);
        }
        #pragma unroll
        for (int m = 16; m; m >>= 1)
            lsum += __shfl_xor_sync(0xffffffffu, lsum, m);
        if (lid == 0) { sLp[w] = lsum; sM[w] = mrun; }
    }
    __syncthreads();

    if (tid < 64) {
        float M4 = sM[0];
        #pragma unroll
        for (int ww = 1; ww < 4; ++ww) M4 = fmaxf(M4, sM[ww]);
        float num = 0.f, l = 0.f;
        #pragma unroll
        for (int ww = 0; ww < 4; ++ww) {
            const float sc = ex2f(sM[ww] - M4);
            num += sc * sRed[ww * 64 + tid];
            l   += sc * sLp[ww];
        }
        g_part[bhq][half][tid] = num;
        if (tid == 0) { g_part[bhq][half][64] = l; g_part[bhq][half][65] = M4; }
    }
}

// ---------------- Combine kernel (4096 x 64) --------------------------------
__global__ void trisimp_combine_kernel(float* __restrict__ out)
{
    const int qv = blockIdx.x, d = threadIdx.x;
    const float m0 = g_part[qv][0][65], m1 = g_part[qv][1][65];
    const float M = fmaxf(m0, m1);
    const float s0 = ex2f(m0 - M), s1 = ex2f(m1 - M);
    const float l = s0 * g_part[qv][0][64] + s1 * g_part[qv][1][64];
    const float n = s0 * g_part[qv][0][d]  + s1 * g_part[qv][1][d];
    out[(size_t)qv * DD + d] = n / l;
}

extern "C" void kernel_launch(void* const* d_in, const int* in_sizes, int n_in,
                              void* d_out, int out_size)
{
    const float* q  = (const float*)d_in[0];
    const float* k1 = (const float*)d_in[1];
    const float* v1 = (const float*)d_in[2];
    const float* k2 = (const float*)d_in[3];
    const float* v2 = (const float*)d_in[4];
    float* out = (float*)d_out;

    (void)cudaFuncSetAttribute(trisimp_half_kernel,
                               cudaFuncAttributeMaxDynamicSharedMemorySize, SMEM_BYTES);
    trisimp_half_kernel<<<2 * 2 * 8 * NQ, 128, SMEM_BYTES>>>(q, k1, v1, k2, v2);
    trisimp_combine_kernel<<<2 * 8 * NQ, 64>>>(out);
}

// round 13
// speedup vs baseline: 1.2157x; 1.2157x over previous
#include <cuda_runtime.h>
#include <cuda_bf16.h>
#include <cuda_fp16.h>
#include <cstdint>

// Fixed shapes: B=2, H=8, N=256, D=64.  One CTA (256 thr, 8 warps) per query.
// Trilinear refactor: S[k,j] = sum_d (q_d*k2[k,d]) * k1[j,d]  -- q folded into K2.
// ALL operands staged ONCE (K2q bf16 hi/lo, K1 bf16 hi/lo, V1 fp16); the panel
// loop has no SMEM writes and no barriers: pure per-warp LDSM/MMA/softmax.
#define NQ 256
#define DD 64
#define NPANEL 4

#define SWZ(x) ((x) ^ (((x) >> 3) & 0x70))

static constexpr uint32_t OFF_K2QH = 0;        // [256 k][64 d] bf16 hi (32 KB)
static constexpr uint32_t OFF_K2QL = 32768;    // lo
static constexpr uint32_t OFF_K1H  = 65536;    // [256 j][64 d] bf16 hi (32 KB)
static constexpr uint32_t OFF_K1L  = 98304;    // lo
static constexpr uint32_t OFF_V1H  = 131072;   // [256 j][64 d] fp16 (32 KB)
static constexpr uint32_t OFF_SRED = 163840;   // [8 warps][64 d] fp32 (2 KB)
static constexpr uint32_t OFF_SLP  = 165888;   // [8] fp32 lsum
static constexpr uint32_t OFF_SM   = 165920;   // [8] fp32 per-warp max
static constexpr uint32_t SMEM_BYTES = 165952;

// ---------------- PTX helpers ----------------------------------------------
__device__ __forceinline__ uint32_t smem_u32(const void* p) {
    uint32_t a;
    asm("{ .reg .u64 t; cvta.to.shared.u64 t, %1; cvt.u32.u64 %0, t; }" : "=r"(a) : "l"(p));
    return a;
}
__device__ __forceinline__ float ex2f(float x) {
    float y; asm("ex2.approx.ftz.f32 %0, %1;" : "=f"(y) : "f"(x)); return y;
}
__device__ __forceinline__ void ldsm_x4(uint32_t* r, uint32_t addr) {
    asm volatile("ldmatrix.sync.aligned.m8n8.x4.shared.b16 {%0,%1,%2,%3}, [%4];"
                 : "=r"(r[0]), "=r"(r[1]), "=r"(r[2]), "=r"(r[3]) : "r"(addr));
}
__device__ __forceinline__ void ldsm_x4_t(uint32_t* r, uint32_t addr) {
    asm volatile("ldmatrix.sync.aligned.m8n8.x4.trans.shared.b16 {%0,%1,%2,%3}, [%4];"
                 : "=r"(r[0]), "=r"(r[1]), "=r"(r[2]), "=r"(r[3]) : "r"(addr));
}
// NOT volatile: pure register ops, scheduler may software-pipeline.
__device__ __forceinline__ void mma_bf(float* c, const uint32_t* a, uint32_t b0, uint32_t b1) {
    asm("mma.sync.aligned.m16n8k16.row.col.f32.bf16.bf16.f32 "
        "{%0,%1,%2,%3}, {%4,%5,%6,%7}, {%8,%9}, {%0,%1,%2,%3};"
        : "+f"(c[0]), "+f"(c[1]), "+f"(c[2]), "+f"(c[3])
        : "r"(a[0]), "r"(a[1]), "r"(a[2]), "r"(a[3]), "r"(b0), "r"(b1));
}
__device__ __forceinline__ void mma_hf(float* c, const uint32_t* a, uint32_t b0, uint32_t b1) {
    asm("mma.sync.aligned.m16n8k16.row.col.f32.f16.f16.f32 "
        "{%0,%1,%2,%3}, {%4,%5,%6,%7}, {%8,%9}, {%0,%1,%2,%3};"
        : "+f"(c[0]), "+f"(c[1]), "+f"(c[2]), "+f"(c[3])
        : "r"(a[0]), "r"(a[1]), "r"(a[2]), "r"(a[3]), "r"(b0), "r"(b1));
}
__device__ __forceinline__ void split2(float x, float y, uint32_t& h, uint32_t& l) {
    __nv_bfloat162 h2 = __floats2bfloat162_rn(x, y);
    __nv_bfloat162 l2 = __floats2bfloat162_rn(x - __low2float(h2), y - __high2float(h2));
    h = *(uint32_t*)&h2; l = *(uint32_t*)&l2;
}
__device__ __forceinline__ uint32_t packh2_sat(float x, float y) {   // x -> low half
    uint32_t r;
    asm("cvt.rn.satfinite.f16x2.f32 %0, %1, %2;" : "=r"(r) : "f"(y), "f"(x));
    return r;
}

// ---------------- Kernel ----------------------------------------------------
__global__ __launch_bounds__(256, 1)
void trisimp_mma6_kernel(const float* __restrict__ q,  const float* __restrict__ k1,
                         const float* __restrict__ v1, const float* __restrict__ k2,
                         const float* __restrict__ v2, float* __restrict__ out)
{
    extern __shared__ char smem[];
    const uint32_t sb = smem_u32(smem);
    const int tid = threadIdx.x, w = tid >> 5, lid = tid & 31;
    const int g = lid >> 2, t = lid & 3;

    const int bhq = blockIdx.x, qi = bhq & 255, bh = bhq >> 8;
    const size_t base = (size_t)bh * NQ * DD;
    const float* Qrow = q  + base + (size_t)qi * DD;
    const float* K1g  = k1 + base;
    const float* V1g  = v1 + base;
    const float* K2g  = k2 + base;
    const float* V2g  = v2 + base;

    const int dp = tid & 31;                     // constant per thread (256 % 32 == 0)
    const float2 qme = ((const float2*)Qrow)[dp];
    const float qx = qme.x * 1.4426950408889634f;
    const float qy = qme.y * 1.4426950408889634f;

    // ---- stage EVERYTHING once: K2q hi/lo, K1 hi/lo, V1 fp16 ----
    {
        const float2* K2g2 = (const float2*)K2g;
        const float2* K1g2 = (const float2*)K1g;
        const float2* V1g2 = (const float2*)V1g;
        for (int e2 = tid; e2 < NQ * 32; e2 += 256) {
            const int r = e2 >> 5;
            const uint32_t off = SWZ((uint32_t)r * 128 + (uint32_t)dp * 4);
            {   // K2q = q * K2 * log2e (bf16 hi/lo)
                const float2 x = K2g2[e2];
                uint32_t h, l; split2(qx * x.x, qy * x.y, h, l);
                *(uint32_t*)(smem + OFF_K2QH + off) = h;
                *(uint32_t*)(smem + OFF_K2QL + off) = l;
            }
            {   // K1 (bf16 hi/lo)
                const float2 x = K1g2[e2];
                uint32_t h, l; split2(x.x, x.y, h, l);
                *(uint32_t*)(smem + OFF_K1H + off) = h;
                *(uint32_t*)(smem + OFF_K1L + off) = l;
            }
            {   // V1 (fp16)
                const float2 x = V1g2[e2];
                const __half2 hh = __floats2half2_rn(x.x, x.y);
                *(uint32_t*)(smem + OFF_V1H + off) = *(const uint32_t*)&hh;
            }
        }
    }
    __syncthreads();                             // the ONLY mainloop barrier

    const uint32_t lmA_r = (uint32_t)(lid & 15), lmA_c = (uint32_t)(lid >> 4) * 16;
    const uint32_t lmB_r = (uint32_t)((lid >> 4) * 8 + (lid & 7)), lmB_c = (uint32_t)((lid >> 3) & 1) * 16;

    float o[2][8][4];
    #pragma unroll
    for (int mt = 0; mt < 2; ++mt)
        #pragma unroll
        for (int nt = 0; nt < 8; ++nt)
            #pragma unroll
            for (int r = 0; r < 4; ++r) o[mt][nt][r] = 0.f;
    float lsum = 0.f;
    float mrun = -1e30f;                         // running per-warp max (log2 units)

    #pragma unroll 1
    for (int p = 0; p < NPANEL; ++p) {
        // ---- GEMM1: S[k32(w), j64(p)] = sum_d K2q[k,d] * K1[j,d]  (3 products) ----
        float s[2][8][4];
        #pragma unroll
        for (int mt = 0; mt < 2; ++mt)
            #pragma unroll
            for (int nt = 0; nt < 8; ++nt)
                #pragma unroll
                for (int r = 0; r < 4; ++r) s[mt][nt][r] = 0.f;

        #pragma unroll
        for (int kc = 0; kc < 4; ++kc) {
            uint32_t aH[2][4], aL[2][4];
            #pragma unroll
            for (int mt = 0; mt < 2; ++mt) {
                const uint32_t rb = (uint32_t)(32 * w + 16 * mt + lmA_r) * 128
                                  + (uint32_t)kc * 32 + lmA_c;
                ldsm_x4(aH[mt], sb + OFF_K2QH + SWZ(rb));
                ldsm_x4(aL[mt], sb + OFF_K2QL + SWZ(rb));
            }
            #pragma unroll
            for (int cp = 0; cp < 4; ++cp) {
                uint32_t bH[4], bL[4];
                const uint32_t rb = (uint32_t)(64 * p + 16 * cp + lmB_r) * 128
                                  + (uint32_t)kc * 32 + lmB_c;
                ldsm_x4(bH, sb + OFF_K1H + SWZ(rb));
                ldsm_x4(bL, sb + OFF_K1L + SWZ(rb));
                #pragma unroll
                for (int h = 0; h < 2; ++h)
                    #pragma unroll
                    for (int mt = 0; mt < 2; ++mt)
                        mma_bf(s[mt][2*cp+h], aH[mt], bH[2*h], bH[2*h+1]);
                #pragma unroll
                for (int h = 0; h < 2; ++h)
                    #pragma unroll
                    for (int mt = 0; mt < 2; ++mt)
                        mma_bf(s[mt][2*cp+h], aH[mt], bL[2*h], bL[2*h+1]);
                #pragma unroll
                for (int h = 0; h < 2; ++h)
                    #pragma unroll
                    for (int mt = 0; mt < 2; ++mt)
                        mma_bf(s[mt][2*cp+h], aL[mt], bH[2*h], bH[2*h+1]);
            }
        }

        // ---- online max update (warp-local; no cross-warp sync) ----
        {
            float pm = s[0][0][0];
            #pragma unroll
            for (int mt = 0; mt < 2; ++mt)
                #pragma unroll
                for (int nt = 0; nt < 8; ++nt)
                    #pragma unroll
                    for (int r = 0; r < 4; ++r) pm = fmaxf(pm, s[mt][nt][r]);
            #pragma unroll
            for (int m = 16; m; m >>= 1)
                pm = fmaxf(pm, __shfl_xor_sync(0xffffffffu, pm, m));
            const float mnew = fmaxf(mrun, pm);
            const float rsc = ex2f(mrun - mnew);  // 0 on first panel
            lsum *= rsc;
            #pragma unroll
            for (int mt = 0; mt < 2; ++mt)
                #pragma unroll
                for (int nt = 0; nt < 8; ++nt)
                    #pragma unroll
                    for (int r = 0; r < 4; ++r) o[mt][nt][r] *= rsc;
            mrun = mnew;
        }

        // ---- exp2(s - m) -> fp16 P, GEMM2 fp16 1-product ----
        #pragma unroll
        for (int c = 0; c < 4; ++c) {
            uint32_t paH[2][4];
            #pragma unroll
            for (int mt = 0; mt < 2; ++mt) {
                #pragma unroll
                for (int h = 0; h < 2; ++h) {
                    float* cc = s[mt][2 * c + h];
                    const float p0 = ex2f(cc[0] - mrun);
                    const float p1 = ex2f(cc[1] - mrun);
                    const float p2 = ex2f(cc[2] - mrun);
                    const float p3 = ex2f(cc[3] - mrun);
                    lsum += (p0 + p1) + (p2 + p3);
                    paH[mt][2*h]   = packh2_sat(p0, p1);   // rows g
                    paH[mt][2*h+1] = packh2_sat(p2, p3);   // rows g+8
                }
            }
            #pragma unroll
            for (int ntp = 0; ntp < 4; ++ntp) {
                uint32_t vH[4];
                const uint32_t rb = (uint32_t)(64 * p + 16 * c + lmA_r) * 128
                                  + (uint32_t)ntp * 32 + lmA_c;
                ldsm_x4_t(vH, sb + OFF_V1H + SWZ(rb));
                #pragma unroll
                for (int h = 0; h < 2; ++h)
                    #pragma unroll
                    for (int mt = 0; mt < 2; ++mt)
                        mma_hf(o[mt][2*ntp+h], paH[mt], vH[2*h], vH[2*h+1]);
            }
        }
    }

    // ---- epilogue: combine warps with per-warp max rescale ----
    float* sRed = (float*)(smem + OFF_SRED);
    float* sLp  = (float*)(smem + OFF_SLP);
    float* sM   = (float*)(smem + OFF_SM);
    {
        const int k0 = 32 * w + g;
        #pragma unroll
        for (int nt = 0; nt < 8; ++nt) {
            const int d0 = 8 * nt + 2 * t;
            const float2 vA = *(const float2*)(V2g + (size_t)(k0)      * DD + d0);
            const float2 vB = *(const float2*)(V2g + (size_t)(k0 + 8)  * DD + d0);
            const float2 vC = *(const float2*)(V2g + (size_t)(k0 + 16) * DD + d0);
            const float2 vD = *(const float2*)(V2g + (size_t)(k0 + 24) * DD + d0);
            float r0 = o[0][nt][0]*vA.x + o[0][nt][2]*vB.x + o[1][nt][0]*vC.x + o[1][nt][2]*vD.x;
            float r1 = o[0][nt][1]*vA.y + o[0][nt][3]*vB.y + o[1][nt][1]*vC.y + o[1][nt][3]*vD.y;
            #pragma unroll
            for (int m = 4; m <= 16; m <<= 1) {
                r0 += __shfl_xor_sync(0xffffffffu, r0, m);
                r1 += __shfl_xor_sync(0xffffffffu, r1, m);
            }
            if (g == 0) *(float2*)(sRed + w * 64 + d0) = make_float2(r0, r1);
        }
        #pragma unroll
        for (int m = 16; m; m >>= 1)
            lsum += __shfl_xor_sync(0xffffffffu, lsum, m);
        if (lid == 0) { sLp[w] = lsum; sM[w] = mrun; }
    }
    __syncthreads();

    if (tid < 64) {
        float M = sM[0];
        #pragma unroll
        for (int ww = 1; ww < 8; ++ww) M = fmaxf(M, sM[ww]);
        float ssum = 0.f, l = 0.f;
        #pragma unroll
        for (int ww = 0; ww < 8; ++ww) {
            const float sc = ex2f(sM[ww] - M);
            ssum += sc * sRed[ww * 64 + tid];
            l    += sc * sLp[ww];
        }
        out[base + (size_t)qi * DD + tid] = ssum / l;
    }
}

extern "C" void kernel_launch(void* const* d_in, const int* in_sizes, int n_in,
                              void* d_out, int out_size)
{
    const float* q  = (const float*)d_in[0];
    const float* k1 = (const float*)d_in[1];
    const float* v1 = (const float*)d_in[2];
    const float* k2 = (const float*)d_in[3];
    const float* v2 = (const float*)d_in[4];
    float* out = (float*)d_out;

    (void)cudaFuncSetAttribute(trisimp_mma6_kernel,
                               cudaFuncAttributeMaxDynamicSharedMemorySize, SMEM_BYTES);
    trisimp_mma6_kernel<<<2 * 8 * NQ, 256, SMEM_BYTES>>>(q, k1, v1, k2, v2, out);
}